// round 1
// baseline (speedup 1.0000x reference)
#include <cuda_runtime.h>
#include <math.h>

#define BSZ 2
#define T   2048
#define E   1024
#define H   16
#define D   64

// Scratch buffers (allocation-free rule: __device__ globals)
__device__ float g_q[BSZ*T*E];
__device__ float g_k[BSZ*T*E];
__device__ float g_v[BSZ*T*E];
__device__ float g_attn[BSZ*T*E];

// ---------------------------------------------------------------------------
// GEMM: C[M,N] = A[M,K] @ W[N,K]^T   (both operands K-contiguous)
// M = BSZ*T = 4096, N = K = E = 1024
// 64x64 tile, BK=16, 256 threads, 4x4 micro-tile per thread.
// ---------------------------------------------------------------------------
#define GBM 64
#define GBN 64
#define GBK 16

__global__ __launch_bounds__(256) void gemm_nt(const float* __restrict__ A,
                                               const float* __restrict__ W,
                                               float* __restrict__ C) {
    const int K = E, N = E;
    __shared__ float As[GBK][GBM];
    __shared__ float Ws[GBK][GBN];

    const int tid = threadIdx.x;
    const int tx = tid & 15;   // N direction
    const int ty = tid >> 4;   // M direction
    const int bm = blockIdx.y * GBM;
    const int bn = blockIdx.x * GBN;

    float acc[4][4] = {};

    const int lr = tid >> 2;       // 0..63 row within tile
    const int lc4 = tid & 3;       // 0..3 -> k sub-chunk of 4

    for (int k0 = 0; k0 < K; k0 += GBK) {
        // Load A tile (64x16) and W tile (64x16), transposed into smem [k][row]
        float4 a4 = *(const float4*)(A + (size_t)(bm + lr) * K + k0 + lc4 * 4);
        float4 w4 = *(const float4*)(W + (size_t)(bn + lr) * K + k0 + lc4 * 4);
        As[lc4*4+0][lr] = a4.x; As[lc4*4+1][lr] = a4.y;
        As[lc4*4+2][lr] = a4.z; As[lc4*4+3][lr] = a4.w;
        Ws[lc4*4+0][lr] = w4.x; Ws[lc4*4+1][lr] = w4.y;
        Ws[lc4*4+2][lr] = w4.z; Ws[lc4*4+3][lr] = w4.w;
        __syncthreads();

        #pragma unroll
        for (int k = 0; k < GBK; k++) {
            float4 a = *(const float4*)&As[k][ty * 4];
            float4 b = *(const float4*)&Ws[k][tx * 4];
            float ar[4] = {a.x, a.y, a.z, a.w};
            float br[4] = {b.x, b.y, b.z, b.w};
            #pragma unroll
            for (int i = 0; i < 4; i++)
                #pragma unroll
                for (int j = 0; j < 4; j++)
                    acc[i][j] = fmaf(ar[i], br[j], acc[i][j]);
        }
        __syncthreads();
    }

    #pragma unroll
    for (int i = 0; i < 4; i++) {
        float4 o = make_float4(acc[i][0], acc[i][1], acc[i][2], acc[i][3]);
        *(float4*)(C + (size_t)(bm + ty * 4 + i) * N + bn + tx * 4) = o;
    }
}

// ---------------------------------------------------------------------------
// Causal flash attention, fp32.
// Grid: (T/AM, BSZ*H). Block: 128 threads.
// Each block: AM=32 query rows. 4 threads per row, each owns 16 of D=64 dims.
// Key tiles of AN=64 staged in smem; only tiles j <= qt/2 are visited (causal).
// ---------------------------------------------------------------------------
#define AM 32
#define AN 64

__global__ __launch_bounds__(128) void attn_kernel() {
    __shared__ float Ks[AN][D];   // 16 KB
    __shared__ float Vs[AN][D];   // 16 KB

    const int tid = threadIdx.x;
    const int bh = blockIdx.y;
    const int b  = bh / H;
    const int h  = bh % H;
    const int qt = blockIdx.x;
    const int qbase = qt * AM;
    const int r  = tid >> 2;      // local query row 0..31
    const int qp = tid & 3;       // dim quarter
    const int qrow = qbase + r;

    // Load this thread's 16 query dims, fold in 1/sqrt(D) = 0.125
    const float* Qp = g_q + ((size_t)(b * T + qrow)) * E + h * D + qp * 16;
    float qreg[16];
    #pragma unroll
    for (int i = 0; i < 16; i++) qreg[i] = Qp[i] * 0.125f;

    float acc[16] = {};
    float m = -INFINITY;
    float l = 0.f;

    const float* Kbase = g_k + ((size_t)(b * T)) * E + h * D;
    const float* Vbase = g_v + ((size_t)(b * T)) * E + h * D;

    const int jmax = qt >> 1;    // inclusive; last tile is the diagonal one
    for (int j = 0; j <= jmax; j++) {
        const int kbase = j * AN;
        // Cooperative K/V tile load: 64 rows x 16 float4 slots = 1024 slots
        #pragma unroll
        for (int i = 0; i < 8; i++) {
            int idx = tid + i * 128;
            int row = idx >> 4;
            int c4  = idx & 15;
            *(float4*)&Ks[row][c4 * 4] =
                *(const float4*)(Kbase + (size_t)(kbase + row) * E + c4 * 4);
            *(float4*)&Vs[row][c4 * 4] =
                *(const float4*)(Vbase + (size_t)(kbase + row) * E + c4 * 4);
        }
        __syncthreads();

        // Scores: s[c] = q . K[c], reduced across the 4-thread quad
        float s[AN];
        #pragma unroll
        for (int c = 0; c < AN; c++) {
            const float4* kr = (const float4*)&Ks[c][qp * 16];
            float p = 0.f;
            #pragma unroll
            for (int i4 = 0; i4 < 4; i4++) {
                float4 kv = kr[i4];
                p = fmaf(qreg[i4*4+0], kv.x, p);
                p = fmaf(qreg[i4*4+1], kv.y, p);
                p = fmaf(qreg[i4*4+2], kv.z, p);
                p = fmaf(qreg[i4*4+3], kv.w, p);
            }
            p += __shfl_xor_sync(0xffffffffu, p, 1);
            p += __shfl_xor_sync(0xffffffffu, p, 2);
            s[c] = p;
        }

        if (j == jmax) {
            #pragma unroll
            for (int c = 0; c < AN; c++)
                if (kbase + c > qrow) s[c] = -INFINITY;
        }

        // Online softmax update
        float mloc = m;
        #pragma unroll
        for (int c = 0; c < AN; c++) mloc = fmaxf(mloc, s[c]);

        float scale = __expf(m - mloc);   // m=-inf, mloc finite -> 0
        l *= scale;
        #pragma unroll
        for (int i = 0; i < 16; i++) acc[i] *= scale;

        #pragma unroll
        for (int c = 0; c < AN; c++) {
            float p = __expf(s[c] - mloc);
            l += p;
            const float4* vr = (const float4*)&Vs[c][qp * 16];
            #pragma unroll
            for (int i4 = 0; i4 < 4; i4++) {
                float4 vv = vr[i4];
                acc[i4*4+0] = fmaf(p, vv.x, acc[i4*4+0]);
                acc[i4*4+1] = fmaf(p, vv.y, acc[i4*4+1]);
                acc[i4*4+2] = fmaf(p, vv.z, acc[i4*4+2]);
                acc[i4*4+3] = fmaf(p, vv.w, acc[i4*4+3]);
            }
        }
        m = mloc;
        __syncthreads();
    }

    const float inv = 1.f / l;
    float* Op = g_attn + ((size_t)(b * T + qrow)) * E + h * D + qp * 16;
    #pragma unroll
    for (int i4 = 0; i4 < 4; i4++) {
        float4 o = make_float4(acc[i4*4+0] * inv, acc[i4*4+1] * inv,
                               acc[i4*4+2] * inv, acc[i4*4+3] * inv);
        *(float4*)(Op + i4 * 4) = o;
    }
}

// ---------------------------------------------------------------------------
// Launch
// Inputs (metadata order): queries, keys, values, mask(unused), Wq, Wk, Wv, Wo
// ---------------------------------------------------------------------------
extern "C" void kernel_launch(void* const* d_in, const int* in_sizes, int n_in,
                              void* d_out, int out_size) {
    const float* queries = (const float*)d_in[0];
    const float* keys    = (const float*)d_in[1];
    const float* values  = (const float*)d_in[2];
    const float* Wq      = (const float*)d_in[4];
    const float* Wk      = (const float*)d_in[5];
    const float* Wv      = (const float*)d_in[6];
    const float* Wo      = (const float*)d_in[7];

    float *q, *k, *v, *attn;
    cudaGetSymbolAddress((void**)&q,    g_q);
    cudaGetSymbolAddress((void**)&k,    g_k);
    cudaGetSymbolAddress((void**)&v,    g_v);
    cudaGetSymbolAddress((void**)&attn, g_attn);

    dim3 gg(E / GBN, (BSZ * T) / GBM);
    gemm_nt<<<gg, 256>>>(queries, Wq, q);
    gemm_nt<<<gg, 256>>>(keys,    Wk, k);
    gemm_nt<<<gg, 256>>>(values,  Wv, v);

    attn_kernel<<<dim3(T / AM, BSZ * H), 128>>>();

    gemm_nt<<<gg, 256>>>(attn, Wo, (float*)d_out);
}

// round 2
// speedup vs baseline: 2.8927x; 2.8927x over previous
#include <cuda_runtime.h>
#include <mma.h>
#include <math.h>

using namespace nvcuda;

#define BSZ 2
#define T   2048
#define E   1024
#define H   16
#define D   64

// Scratch (allocation-free rule: __device__ globals)
__device__ float g_q[BSZ*T*E];
__device__ float g_k[BSZ*T*E];
__device__ float g_v[BSZ*T*E];
__device__ float g_attn[BSZ*T*E];

template <class Frag>
__device__ __forceinline__ void cvt_tf32(Frag& f) {
    #pragma unroll
    for (int i = 0; i < f.num_elements; i++)
        f.x[i] = wmma::__float_to_tf32(f.x[i]);
}

// ---------------------------------------------------------------------------
// GEMM: C[M,N] = A[M,K] @ W[N,K]^T, tf32 wmma, fp32 accum.
// M=4096, N=K=1024. 128x128 tile, BK=16, 256 threads (8 warps, warp=32x64).
// ---------------------------------------------------------------------------
__global__ __launch_bounds__(256) void gemm_tc(const float* __restrict__ A,
                                               const float* __restrict__ W,
                                               float* __restrict__ C) {
    const int K = E, N = E;
    __shared__ float As[128][20];
    __shared__ float Ws[128][20];

    const int tid = threadIdx.x;
    const int warpId = tid >> 5;
    const int wr = warpId & 3;   // row group: 32 rows
    const int wc = warpId >> 2;  // col group: 64 cols
    const int bm = blockIdx.y * 128;
    const int bn = blockIdx.x * 128;

    wmma::fragment<wmma::accumulator, 16, 16, 8, float> acc[2][4];
    #pragma unroll
    for (int mi = 0; mi < 2; mi++)
        #pragma unroll
        for (int ni = 0; ni < 4; ni++)
            wmma::fill_fragment(acc[mi][ni], 0.0f);

    for (int k0 = 0; k0 < K; k0 += 16) {
        #pragma unroll
        for (int t = 0; t < 2; t++) {
            int slot = tid + t * 256;
            int row = slot >> 2;
            int c4  = slot & 3;
            float4 a4 = *(const float4*)(A + (size_t)(bm + row) * K + k0 + c4 * 4);
            float4 w4 = *(const float4*)(W + (size_t)(bn + row) * K + k0 + c4 * 4);
            *(float4*)&As[row][c4 * 4] = a4;
            *(float4*)&Ws[row][c4 * 4] = w4;
        }
        __syncthreads();

        #pragma unroll
        for (int kk = 0; kk < 2; kk++) {
            wmma::fragment<wmma::matrix_a, 16, 16, 8, wmma::precision::tf32, wmma::row_major> af[2];
            wmma::fragment<wmma::matrix_b, 16, 16, 8, wmma::precision::tf32, wmma::col_major> bf[4];
            #pragma unroll
            for (int mi = 0; mi < 2; mi++) {
                wmma::load_matrix_sync(af[mi], &As[wr * 32 + mi * 16][kk * 8], 20);
                cvt_tf32(af[mi]);
            }
            #pragma unroll
            for (int ni = 0; ni < 4; ni++) {
                wmma::load_matrix_sync(bf[ni], &Ws[wc * 64 + ni * 16][kk * 8], 20);
                cvt_tf32(bf[ni]);
            }
            #pragma unroll
            for (int mi = 0; mi < 2; mi++)
                #pragma unroll
                for (int ni = 0; ni < 4; ni++)
                    wmma::mma_sync(acc[mi][ni], af[mi], bf[ni], acc[mi][ni]);
        }
        __syncthreads();
    }

    #pragma unroll
    for (int mi = 0; mi < 2; mi++)
        #pragma unroll
        for (int ni = 0; ni < 4; ni++)
            wmma::store_matrix_sync(
                C + (size_t)(bm + wr * 32 + mi * 16) * N + bn + wc * 64 + ni * 16,
                acc[mi][ni], N, wmma::mem_row_major);
}

// ---------------------------------------------------------------------------
// Causal flash attention, tf32 wmma.
// Block: 128 threads (4 warps), 64 query rows, 64-key tiles.
// Warp w owns rows [w*16, w*16+16). O tile lives in smem (enables per-row
// online-softmax rescale despite opaque accumulator layout).
// Dynamic smem: Ks, Vs, Ss, Os each [64][72] fp32 = 72 KB.
// ---------------------------------------------------------------------------
#define AP 72          // padded row stride
#define ATILE (64*AP)

__global__ __launch_bounds__(128) void attn_tc() {
    extern __shared__ float smx[];
    float (*Ks)[AP] = (float(*)[AP])(smx);
    float (*Vs)[AP] = (float(*)[AP])(smx + ATILE);
    float (*Ss)[AP] = (float(*)[AP])(smx + 2 * ATILE);
    float (*Os)[AP] = (float(*)[AP])(smx + 3 * ATILE);

    const int tid  = threadIdx.x;
    const int w    = tid >> 5;
    const int lane = tid & 31;
    const int b    = blockIdx.y / H;
    const int h    = blockIdx.y % H;
    const int qt   = blockIdx.x;
    const int qbase = qt * 64;

    const float* Qg = g_q + ((size_t)(b * T + qbase)) * E + h * D;
    const float* Kg = g_k + ((size_t)(b * T)) * E + h * D;
    const float* Vg = g_v + ((size_t)(b * T)) * E + h * D;

    // Stage Q (scaled by 1/sqrt(D)) into Ks buffer, then lift into fragments.
    #pragma unroll
    for (int t = 0; t < 8; t++) {
        int slot = tid + t * 128;
        int row = slot >> 4, c4 = slot & 15;
        float4 v = *(const float4*)(Qg + (size_t)row * E + c4 * 4);
        v.x *= 0.125f; v.y *= 0.125f; v.z *= 0.125f; v.w *= 0.125f;
        *(float4*)&Ks[row][c4 * 4] = v;
    }
    __syncthreads();

    wmma::fragment<wmma::matrix_a, 16, 16, 8, wmma::precision::tf32, wmma::row_major> qa[8];
    #pragma unroll
    for (int kk = 0; kk < 8; kk++) {
        wmma::load_matrix_sync(qa[kk], &Ks[w * 16][kk * 8], AP);
        cvt_tf32(qa[kk]);
    }
    // Clear O tile
    for (int i = tid; i < ATILE; i += 128) (smx + 3 * ATILE)[i] = 0.f;

    const int srow = w * 16 + (lane >> 1);   // this lane's softmax row
    const int half = (lane & 1) * 32;        // col half this lane owns
    const int qglob = qbase + srow;
    float mrow = -INFINITY, lrow = 0.f;

    for (int j = 0; j <= qt; j++) {
        __syncthreads();   // prior iter's PV reads of Vs/Ss done; Os cleared (iter 0)
        const int kbase = j * 64;
        #pragma unroll
        for (int t = 0; t < 8; t++) {
            int slot = tid + t * 128;
            int row = slot >> 4, c4 = slot & 15;
            *(float4*)&Ks[row][c4 * 4] =
                *(const float4*)(Kg + (size_t)(kbase + row) * E + c4 * 4);
            *(float4*)&Vs[row][c4 * 4] =
                *(const float4*)(Vg + (size_t)(kbase + row) * E + c4 * 4);
        }
        __syncthreads();

        // S = Q @ K^T  (warp computes its 16x64 strip)
        wmma::fragment<wmma::accumulator, 16, 16, 8, float> sacc[4];
        #pragma unroll
        for (int ni = 0; ni < 4; ni++) wmma::fill_fragment(sacc[ni], 0.0f);
        #pragma unroll
        for (int kk = 0; kk < 8; kk++) {
            #pragma unroll
            for (int ni = 0; ni < 4; ni++) {
                wmma::fragment<wmma::matrix_b, 16, 16, 8, wmma::precision::tf32, wmma::col_major> kb;
                wmma::load_matrix_sync(kb, &Ks[ni * 16][kk * 8], AP);
                cvt_tf32(kb);
                wmma::mma_sync(sacc[ni], qa[kk], kb, sacc[ni]);
            }
        }
        #pragma unroll
        for (int ni = 0; ni < 4; ni++)
            wmma::store_matrix_sync(&Ss[w * 16][ni * 16], sacc[ni], AP, wmma::mem_row_major);
        __syncwarp();

        // Online softmax on warp-private rows (2 lanes per row, 32 cols each)
        const bool diag = (j == qt);
        float mx = -INFINITY;
        #pragma unroll
        for (int c = 0; c < 32; c++) {
            float v = Ss[srow][half + c];
            if (diag && (kbase + half + c > qglob)) { v = -INFINITY; Ss[srow][half + c] = v; }
            mx = fmaxf(mx, v);
        }
        mx = fmaxf(mx, __shfl_xor_sync(0xffffffffu, mx, 1));
        float mnew  = fmaxf(mrow, mx);
        float scale = __expf(mrow - mnew);
        float sum = 0.f;
        #pragma unroll
        for (int c = 0; c < 32; c++) {
            float p = __expf(Ss[srow][half + c] - mnew);
            Ss[srow][half + c] = p;
            sum += p;
        }
        sum += __shfl_xor_sync(0xffffffffu, sum, 1);
        lrow = lrow * scale + sum;
        mrow = mnew;
        #pragma unroll
        for (int c = 0; c < 32; c += 4) {
            float4 o = *(float4*)&Os[srow][half + c];
            o.x *= scale; o.y *= scale; o.z *= scale; o.w *= scale;
            *(float4*)&Os[srow][half + c] = o;
        }
        __syncwarp();

        // O += P @ V
        wmma::fragment<wmma::matrix_a, 16, 16, 8, wmma::precision::tf32, wmma::row_major> pa[8];
        #pragma unroll
        for (int kk = 0; kk < 8; kk++) {
            wmma::load_matrix_sync(pa[kk], &Ss[w * 16][kk * 8], AP);
            cvt_tf32(pa[kk]);
        }
        #pragma unroll
        for (int ni = 0; ni < 4; ni++) {
            wmma::fragment<wmma::accumulator, 16, 16, 8, float> oacc;
            wmma::load_matrix_sync(oacc, &Os[w * 16][ni * 16], AP, wmma::mem_row_major);
            #pragma unroll
            for (int kk = 0; kk < 8; kk++) {
                wmma::fragment<wmma::matrix_b, 16, 16, 8, wmma::precision::tf32, wmma::row_major> vb;
                wmma::load_matrix_sync(vb, &Vs[kk * 8][ni * 16], AP);
                cvt_tf32(vb);
                wmma::mma_sync(oacc, pa[kk], vb, oacc);
            }
            wmma::store_matrix_sync(&Os[w * 16][ni * 16], oacc, AP, wmma::mem_row_major);
        }
    }

    __syncwarp();
    const float inv = 1.f / lrow;
    float* Og = g_attn + ((size_t)(b * T + qglob)) * E + h * D + half;
    #pragma unroll
    for (int c = 0; c < 32; c += 4) {
        float4 o = *(float4*)&Os[srow][half + c];
        o.x *= inv; o.y *= inv; o.z *= inv; o.w *= inv;
        *(float4*)(Og + c) = o;
    }
}

// ---------------------------------------------------------------------------
// Inputs (metadata order): queries, keys, values, mask(unused), Wq, Wk, Wv, Wo
// ---------------------------------------------------------------------------
extern "C" void kernel_launch(void* const* d_in, const int* in_sizes, int n_in,
                              void* d_out, int out_size) {
    const float* queries = (const float*)d_in[0];
    const float* keys    = (const float*)d_in[1];
    const float* values  = (const float*)d_in[2];
    const float* Wq      = (const float*)d_in[4];
    const float* Wk      = (const float*)d_in[5];
    const float* Wv      = (const float*)d_in[6];
    const float* Wo      = (const float*)d_in[7];

    float *q, *k, *v, *attn;
    cudaGetSymbolAddress((void**)&q,    g_q);
    cudaGetSymbolAddress((void**)&k,    g_k);
    cudaGetSymbolAddress((void**)&v,    g_v);
    cudaGetSymbolAddress((void**)&attn, g_attn);

    static bool attr_set = false;
    if (!attr_set) {
        cudaFuncSetAttribute(attn_tc, cudaFuncAttributeMaxDynamicSharedMemorySize,
                             4 * ATILE * (int)sizeof(float));
        attr_set = true;
    }

    dim3 gg(E / 128, (BSZ * T) / 128);
    gemm_tc<<<gg, 256>>>(queries, Wq, q);
    gemm_tc<<<gg, 256>>>(keys,    Wk, k);
    gemm_tc<<<gg, 256>>>(values,  Wv, v);

    attn_tc<<<dim3(T / 64, BSZ * H), 128, 4 * ATILE * sizeof(float)>>>();

    gemm_tc<<<gg, 256>>>(attn, Wo, (float*)d_out);
}

// round 3
// speedup vs baseline: 3.0927x; 1.0691x over previous
#include <cuda_runtime.h>
#include <mma.h>
#include <math.h>
#include <stdint.h>

using namespace nvcuda;

#define BSZ 2
#define T   2048
#define E   1024
#define H   16
#define D   64

__device__ float g_q[BSZ*T*E];
__device__ float g_k[BSZ*T*E];
__device__ float g_v[BSZ*T*E];
__device__ float g_attn[BSZ*T*E];

__device__ __forceinline__ float tf32f(float x) {
    uint32_t u;
    asm("cvt.rna.tf32.f32 %0, %1;" : "=r"(u) : "f"(x));
    return __uint_as_float(u);
}
__device__ __forceinline__ uint32_t tf32u(float x) {
    uint32_t u;
    asm("cvt.rna.tf32.f32 %0, %1;" : "=r"(u) : "f"(x));
    return u;
}
__device__ __forceinline__ void mma8(float c[4], const uint32_t a[4],
                                     uint32_t b0, uint32_t b1) {
    asm("mma.sync.aligned.m16n8k8.row.col.f32.tf32.tf32.f32 "
        "{%0,%1,%2,%3},{%4,%5,%6,%7},{%8,%9},{%0,%1,%2,%3};"
        : "+f"(c[0]), "+f"(c[1]), "+f"(c[2]), "+f"(c[3])
        : "r"(a[0]), "r"(a[1]), "r"(a[2]), "r"(a[3]), "r"(b0), "r"(b1));
}

// ---------------------------------------------------------------------------
// GEMM: C[M,N] = A[M,K] @ W[N,K]^T, tf32 wmma, fp32 accum.
// 128x128 tile, BK=32, 256 threads, double-buffered smem, tf32 cvt at staging.
// ---------------------------------------------------------------------------
#define GP 36                       // padded k-stride (floats)
#define GBUF (128*GP)               // one tile buffer
#define GSMEM (4*GBUF*sizeof(float))

__global__ __launch_bounds__(256) void gemm_tc(const float* __restrict__ A,
                                               const float* __restrict__ W,
                                               float* __restrict__ C) {
    const int K = E, N = E;
    extern __shared__ float sg[];
    float* As = sg;           // [2][128][GP]
    float* Ws = sg + 2*GBUF;  // [2][128][GP]

    const int tid = threadIdx.x;
    const int warpId = tid >> 5;
    const int wr = warpId & 3;
    const int wc = warpId >> 2;
    const int bm = blockIdx.y * 128;
    const int bn = blockIdx.x * 128;

    wmma::fragment<wmma::accumulator, 16, 16, 8, float> acc[2][4];
    #pragma unroll
    for (int mi = 0; mi < 2; mi++)
        #pragma unroll
        for (int ni = 0; ni < 4; ni++)
            wmma::fill_fragment(acc[mi][ni], 0.0f);

    float4 ra[4], rw[4];
    auto ldg = [&](int kt) {
        #pragma unroll
        for (int t = 0; t < 4; t++) {
            int slot = tid + t * 256;       // 0..1023
            int row = slot >> 3, c4 = slot & 7;
            ra[t] = *(const float4*)(A + (size_t)(bm + row) * K + kt * 32 + c4 * 4);
            rw[t] = *(const float4*)(W + (size_t)(bn + row) * K + kt * 32 + c4 * 4);
        }
    };
    auto sts = [&](int buf) {
        #pragma unroll
        for (int t = 0; t < 4; t++) {
            int slot = tid + t * 256;
            int row = slot >> 3, c4 = slot & 7;
            float* da = &As[buf * GBUF + row * GP + c4 * 4];
            float* dw = &Ws[buf * GBUF + row * GP + c4 * 4];
            da[0] = tf32f(ra[t].x); da[1] = tf32f(ra[t].y);
            da[2] = tf32f(ra[t].z); da[3] = tf32f(ra[t].w);
            dw[0] = tf32f(rw[t].x); dw[1] = tf32f(rw[t].y);
            dw[2] = tf32f(rw[t].z); dw[3] = tf32f(rw[t].w);
        }
    };
    auto compute = [&](int buf) {
        #pragma unroll
        for (int kb = 0; kb < 4; kb++) {
            wmma::fragment<wmma::matrix_a, 16, 16, 8, wmma::precision::tf32, wmma::row_major> af[2];
            wmma::fragment<wmma::matrix_b, 16, 16, 8, wmma::precision::tf32, wmma::col_major> bf[4];
            #pragma unroll
            for (int mi = 0; mi < 2; mi++)
                wmma::load_matrix_sync(af[mi], &As[buf*GBUF + (wr*32 + mi*16)*GP + kb*8], GP);
            #pragma unroll
            for (int ni = 0; ni < 4; ni++)
                wmma::load_matrix_sync(bf[ni], &Ws[buf*GBUF + (wc*64 + ni*16)*GP + kb*8], GP);
            #pragma unroll
            for (int mi = 0; mi < 2; mi++)
                #pragma unroll
                for (int ni = 0; ni < 4; ni++)
                    wmma::mma_sync(acc[mi][ni], af[mi], bf[ni], acc[mi][ni]);
        }
    };

    ldg(0); sts(0); __syncthreads();
    for (int kt = 0; kt < 32; kt++) {
        if (kt < 31) ldg(kt + 1);
        compute(kt & 1);
        if (kt < 31) { sts((kt + 1) & 1); __syncthreads(); }
    }

    #pragma unroll
    for (int mi = 0; mi < 2; mi++)
        #pragma unroll
        for (int ni = 0; ni < 4; ni++)
            wmma::store_matrix_sync(
                C + (size_t)(bm + wr*32 + mi*16) * N + bn + wc*64 + ni*16,
                acc[mi][ni], N, wmma::mem_row_major);
}

// ---------------------------------------------------------------------------
// Register-resident causal flash attention, mma.m16n8k8 tf32 PTX.
// Block: 128 threads (4 warps), Q tile 64 rows (16/warp), key tiles of 64.
// K/V staged in fragment-permuted smem (one LDS.64 per B-fragment),
// S / softmax / P / O entirely in registers.
// ---------------------------------------------------------------------------
__global__ __launch_bounds__(128) void attn_tc() {
    __shared__ float sm[8192];   // KsB: [0,4096)  VsB: [4096,8192)

    const int tid = threadIdx.x;
    const int w = tid >> 5, lane = tid & 31;
    const int g = lane >> 2, q = lane & 3;
    const int b = blockIdx.y / H, h = blockIdx.y % H;
    const int qt = blockIdx.x;
    const int qbase = qt * 64;

    const float* Qg = g_q + ((size_t)(b * T + qbase)) * E + h * D;
    const float* Kg = g_k + (size_t)b * T * E + h * D;
    const float* Vg = g_v + (size_t)b * T * E + h * D;

    // Stage Q (x0.125, tf32) into smem overlay [64][65], lift to A fragments.
    #pragma unroll
    for (int t = 0; t < 8; t++) {
        int slot = tid + t * 128;
        int row = slot >> 4, c4 = slot & 15;
        float4 v = *(const float4*)(Qg + (size_t)row * E + c4 * 4);
        float* dst = &sm[row * 65 + c4 * 4];
        dst[0] = tf32f(v.x * 0.125f); dst[1] = tf32f(v.y * 0.125f);
        dst[2] = tf32f(v.z * 0.125f); dst[3] = tf32f(v.w * 0.125f);
    }
    __syncthreads();

    const int r0 = w * 16 + g;          // local row
    uint32_t qa[8][4];
    #pragma unroll
    for (int kc = 0; kc < 8; kc++) {
        qa[kc][0] = __float_as_uint(sm[r0 * 65 + kc * 8 + q]);
        qa[kc][1] = __float_as_uint(sm[(r0 + 8) * 65 + kc * 8 + q]);
        qa[kc][2] = __float_as_uint(sm[r0 * 65 + kc * 8 + q + 4]);
        qa[kc][3] = __float_as_uint(sm[(r0 + 8) * 65 + kc * 8 + q + 4]);
    }

    float oacc[8][4];
    #pragma unroll
    for (int nt = 0; nt < 8; nt++)
        #pragma unroll
        for (int e = 0; e < 4; e++) oacc[nt][e] = 0.f;

    float m0 = -INFINITY, m1 = -INFINITY, l0 = 0.f, l1 = 0.f;
    const int r0g = qbase + r0, r1g = r0g + 8;
    const int s0l = (lane & ~3) | (q >> 1);
    const int s1l = s0l + 2;

    for (int j = 0; j <= qt; j++) {
        __syncthreads();                 // previous tile fully consumed
        const int kbase = j * 64;
        // Stage K/V tile into fragment-permuted layout, tf32-converted.
        #pragma unroll
        for (int t = 0; t < 8; t++) {
            int slot = tid + t * 128;
            int row = slot >> 4, c4 = slot & 15;
            float4 kv = *(const float4*)(Kg + (size_t)(kbase + row) * E + c4 * 4);
            float4 vv = *(const float4*)(Vg + (size_t)(kbase + row) * E + c4 * 4);
            float ke[4] = {kv.x, kv.y, kv.z, kv.w};
            float ve[4] = {vv.x, vv.y, vv.z, vv.w};
            #pragma unroll
            for (int ee = 0; ee < 4; ee++) {
                int col = c4 * 4 + ee;
                // K: (n=keyrow, k=dim) B-fragment slot
                int nt = row >> 3, kc = col >> 3;
                int ln = ((row & 7) << 2) | (col & 3);
                int e  = (col >> 2) & 1;
                sm[((nt * 8 + kc) * 32 + ln) * 2 + e] = tf32f(ke[ee]);
                // V: (k=keyrow, n=dim) B-fragment slot
                int kc2 = row >> 3, e2 = (row >> 2) & 1;
                int nt2 = col >> 3;
                int ln2 = ((col & 7) << 2) | (row & 3);
                sm[4096 + ((nt2 * 8 + kc2) * 32 + ln2) * 2 + e2] = tf32f(ve[ee]);
            }
        }
        __syncthreads();

        // S = Q @ K^T (registers)
        float sacc[8][4];
        #pragma unroll
        for (int nt = 0; nt < 8; nt++) {
            #pragma unroll
            for (int e = 0; e < 4; e++) sacc[nt][e] = 0.f;
            #pragma unroll
            for (int kc = 0; kc < 8; kc++) {
                float2 bb = *(const float2*)&sm[((nt * 8 + kc) * 32 + lane) * 2];
                mma8(sacc[nt], qa[kc], __float_as_uint(bb.x), __float_as_uint(bb.y));
            }
        }

        // Causal mask (diagonal tile only)
        if (j == qt) {
            #pragma unroll
            for (int nt = 0; nt < 8; nt++) {
                #pragma unroll
                for (int e = 0; e < 2; e++) {
                    int colg = kbase + nt * 8 + 2 * q + e;
                    if (colg > r0g) sacc[nt][e]     = -INFINITY;
                    if (colg > r1g) sacc[nt][2 + e] = -INFINITY;
                }
            }
        }

        // Online softmax (registers + quad shuffles)
        float mx0 = -INFINITY, mx1 = -INFINITY;
        #pragma unroll
        for (int nt = 0; nt < 8; nt++) {
            mx0 = fmaxf(mx0, fmaxf(sacc[nt][0], sacc[nt][1]));
            mx1 = fmaxf(mx1, fmaxf(sacc[nt][2], sacc[nt][3]));
        }
        mx0 = fmaxf(mx0, __shfl_xor_sync(0xffffffffu, mx0, 1));
        mx0 = fmaxf(mx0, __shfl_xor_sync(0xffffffffu, mx0, 2));
        mx1 = fmaxf(mx1, __shfl_xor_sync(0xffffffffu, mx1, 1));
        mx1 = fmaxf(mx1, __shfl_xor_sync(0xffffffffu, mx1, 2));
        float mn0 = fmaxf(m0, mx0), mn1 = fmaxf(m1, mx1);
        float sc0 = __expf(m0 - mn0), sc1 = __expf(m1 - mn1);

        float s0 = 0.f, s1 = 0.f;
        uint32_t pb[8][4];
        #pragma unroll
        for (int nt = 0; nt < 8; nt++) {
            float p0 = __expf(sacc[nt][0] - mn0);
            float p1 = __expf(sacc[nt][1] - mn0);
            float p2 = __expf(sacc[nt][2] - mn1);
            float p3 = __expf(sacc[nt][3] - mn1);
            s0 += p0 + p1; s1 += p2 + p3;
            pb[nt][0] = tf32u(p0); pb[nt][1] = tf32u(p1);
            pb[nt][2] = tf32u(p2); pb[nt][3] = tf32u(p3);
        }
        s0 += __shfl_xor_sync(0xffffffffu, s0, 1);
        s0 += __shfl_xor_sync(0xffffffffu, s0, 2);
        s1 += __shfl_xor_sync(0xffffffffu, s1, 1);
        s1 += __shfl_xor_sync(0xffffffffu, s1, 2);
        l0 = l0 * sc0 + s0; l1 = l1 * sc1 + s1;
        m0 = mn0; m1 = mn1;
        #pragma unroll
        for (int nt = 0; nt < 8; nt++) {
            oacc[nt][0] *= sc0; oacc[nt][1] *= sc0;
            oacc[nt][2] *= sc1; oacc[nt][3] *= sc1;
        }

        // O += P @ V : transpose P acc-layout -> A-layout via quad shuffles
        #pragma unroll
        for (int kc = 0; kc < 8; kc++) {
            uint32_t v00 = __shfl_sync(0xffffffffu, pb[kc][0], s0l);
            uint32_t v01 = __shfl_sync(0xffffffffu, pb[kc][1], s0l);
            uint32_t v10 = __shfl_sync(0xffffffffu, pb[kc][2], s0l);
            uint32_t v11 = __shfl_sync(0xffffffffu, pb[kc][3], s0l);
            uint32_t v20 = __shfl_sync(0xffffffffu, pb[kc][0], s1l);
            uint32_t v21 = __shfl_sync(0xffffffffu, pb[kc][1], s1l);
            uint32_t v30 = __shfl_sync(0xffffffffu, pb[kc][2], s1l);
            uint32_t v31 = __shfl_sync(0xffffffffu, pb[kc][3], s1l);
            uint32_t pa[4];
            pa[0] = (q & 1) ? v01 : v00;
            pa[1] = (q & 1) ? v11 : v10;
            pa[2] = (q & 1) ? v21 : v20;
            pa[3] = (q & 1) ? v31 : v30;
            #pragma unroll
            for (int nt = 0; nt < 8; nt++) {
                float2 bb = *(const float2*)&sm[4096 + ((nt * 8 + kc) * 32 + lane) * 2];
                mma8(oacc[nt], pa, __float_as_uint(bb.x), __float_as_uint(bb.y));
            }
        }
    }

    const float inv0 = 1.f / l0, inv1 = 1.f / l1;
    float* O0 = g_attn + ((size_t)(b * T + r0g)) * E + h * D;
    float* O1 = g_attn + ((size_t)(b * T + r1g)) * E + h * D;
    #pragma unroll
    for (int nt = 0; nt < 8; nt++) {
        O0[nt * 8 + 2 * q]     = oacc[nt][0] * inv0;
        O0[nt * 8 + 2 * q + 1] = oacc[nt][1] * inv0;
        O1[nt * 8 + 2 * q]     = oacc[nt][2] * inv1;
        O1[nt * 8 + 2 * q + 1] = oacc[nt][3] * inv1;
    }
}

// ---------------------------------------------------------------------------
// Inputs: queries, keys, values, mask(unused), Wq, Wk, Wv, Wo
// ---------------------------------------------------------------------------
extern "C" void kernel_launch(void* const* d_in, const int* in_sizes, int n_in,
                              void* d_out, int out_size) {
    const float* queries = (const float*)d_in[0];
    const float* keys    = (const float*)d_in[1];
    const float* values  = (const float*)d_in[2];
    const float* Wq      = (const float*)d_in[4];
    const float* Wk      = (const float*)d_in[5];
    const float* Wv      = (const float*)d_in[6];
    const float* Wo      = (const float*)d_in[7];

    float *qp, *kp, *vp, *ap;
    cudaGetSymbolAddress((void**)&qp, g_q);
    cudaGetSymbolAddress((void**)&kp, g_k);
    cudaGetSymbolAddress((void**)&vp, g_v);
    cudaGetSymbolAddress((void**)&ap, g_attn);

    static bool attr_set = false;
    if (!attr_set) {
        cudaFuncSetAttribute(gemm_tc, cudaFuncAttributeMaxDynamicSharedMemorySize,
                             (int)GSMEM);
        attr_set = true;
    }

    dim3 gg(E / 128, (BSZ * T) / 128);
    gemm_tc<<<gg, 256, GSMEM>>>(queries, Wq, qp);
    gemm_tc<<<gg, 256, GSMEM>>>(keys,    Wk, kp);
    gemm_tc<<<gg, 256, GSMEM>>>(values,  Wv, vp);

    attn_tc<<<dim3(T / 64, BSZ * H), 128>>>();

    gemm_tc<<<gg, 256, GSMEM>>>(ap, Wo, (float*)d_out);
}

// round 7
// speedup vs baseline: 4.8463x; 1.5670x over previous
#include <cuda_runtime.h>
#include <math.h>
#include <stdint.h>

#define BSZ 2
#define T   2048
#define E   1024
#define H   16
#define D   64

__device__ float g_q[BSZ*T*E];
__device__ float g_k[BSZ*T*E];
__device__ float g_v[BSZ*T*E];
__device__ float g_attn[BSZ*T*E];

// ===========================================================================
// Helpers
// ===========================================================================
__device__ __forceinline__ uint32_t su32(const void* p) {
    return (uint32_t)__cvta_generic_to_shared(p);
}
__device__ __forceinline__ float tf32f(float x) {
    uint32_t u; asm("cvt.rna.tf32.f32 %0, %1;" : "=r"(u) : "f"(x));
    return __uint_as_float(u);
}
__device__ __forceinline__ uint32_t tf32u(float x) {
    uint32_t u; asm("cvt.rna.tf32.f32 %0, %1;" : "=r"(u) : "f"(x));
    return u;
}
__device__ __forceinline__ void mma8(float c[4], const uint32_t a[4],
                                     uint32_t b0, uint32_t b1) {
    asm("mma.sync.aligned.m16n8k8.row.col.f32.tf32.tf32.f32 "
        "{%0,%1,%2,%3},{%4,%5,%6,%7},{%8,%9},{%0,%1,%2,%3};"
        : "+f"(c[0]), "+f"(c[1]), "+f"(c[2]), "+f"(c[3])
        : "r"(a[0]), "r"(a[1]), "r"(a[2]), "r"(a[3]), "r"(b0), "r"(b1));
}
__device__ __forceinline__ void cp16(uint32_t dst, const void* src) {
    asm volatile("cp.async.cg.shared.global [%0], [%1], 16;"
                 :: "r"(dst), "l"(src) : "memory");
}
__device__ __forceinline__ void cp_commit() {
    asm volatile("cp.async.commit_group;" ::: "memory");
}
template <int N>
__device__ __forceinline__ void cp_wait() {
    asm volatile("cp.async.wait_group %0;" :: "n"(N) : "memory");
}

// ===========================================================================
// tf32 mma.sync GEMM: C[M,N] = A[M,K] @ W[N,K]^T
// M=4096, N=K=1024. CTA 128x256, 512 threads = 16 warps, warp tile 32x64
// (wr = wid&3 -> 4 x 32 rows, wc = wid>>2 -> 4 x 64 cols: FULL tile, fixing
// the R5/R6 bug where 8 warps covered only 128x128 and half the tile was
// never written). BK=32, cp.async 4-stage pipe, rna tf32 at fragment load.
// ===========================================================================
#define KDIM 1024
#define MT   128
#define NT   256
#define BKF  32
#define NSTG 4
#define GPAD 36                              // padded row stride (floats)
#define G_AOFF 0
#define G_WOFF (MT*GPAD*4)                   // 18432 B
#define G_STAGE ((MT+NT)*GPAD*4)             // 55296 B
#define G_SMEM (NSTG*G_STAGE)                // 221184 B

__global__ __launch_bounds__(512, 1) void gemm_mma(const float* __restrict__ A,
                                                   const float* __restrict__ W,
                                                   float* __restrict__ C) {
    extern __shared__ float sg[];
    const uint32_t sbase = su32(sg);
    const int tid  = threadIdx.x;
    const int wid  = tid >> 5, lane = tid & 31;
    const int g    = lane >> 2, q = lane & 3;
    const int wr   = wid & 3;          // m group (32 rows)  0..3
    const int wc   = wid >> 2;         // n group (64 cols)  0..3
    const int bm   = blockIdx.y * MT;
    const int bn   = blockIdx.x * NT;

    const float* gA = A + (size_t)bm * KDIM;
    const float* gW = W + (size_t)bn * KDIM;

    auto cp_stage = [&](int s, int kt) {
        const uint32_t base = sbase + s * G_STAGE;
        const int k0 = kt * BKF;
        #pragma unroll
        for (int i = 0; i < 6; i++) {
            int c = tid + i * 512;                  // 0..3071
            if (c < 1024) {                          // A: 128 rows x 8 chunks
                int row = c >> 3, ch = c & 7;
                cp16(base + G_AOFF + (row * GPAD + ch * 4) * 4,
                     gA + (size_t)row * KDIM + k0 + ch * 4);
            } else {                                 // W: 256 rows x 8 chunks
                int cc = c - 1024;
                int row = cc >> 3, ch = cc & 7;
                cp16(base + G_WOFF + (row * GPAD + ch * 4) * 4,
                     gW + (size_t)row * KDIM + k0 + ch * 4);
            }
        }
        cp_commit();
    };

    float acc[2][8][4];
    #pragma unroll
    for (int mi = 0; mi < 2; mi++)
        #pragma unroll
        for (int ni = 0; ni < 8; ni++)
            #pragma unroll
            for (int e = 0; e < 4; e++) acc[mi][ni][e] = 0.f;

    cp_stage(0, 0); cp_stage(1, 1); cp_stage(2, 2);

    const int NKT = KDIM / BKF;   // 32
    for (int kt = 0; kt < NKT; kt++) {
        cp_wait<2>();
        __syncthreads();
        if (kt + 3 < NKT) cp_stage((kt + 3) & 3, kt + 3);
        else              cp_commit();       // keep wait-group math valid in tail

        const float* As = sg + ((kt & 3) * G_STAGE) / 4;
        const float* Ws = As + MT * GPAD;
        const int m0 = wr * 32, n0 = wc * 64;

        #pragma unroll
        for (int kc = 0; kc < 4; kc++) {
            uint32_t af[2][4];
            #pragma unroll
            for (int mi = 0; mi < 2; mi++) {
                const float* ap = As + (m0 + mi * 16 + g) * GPAD + kc * 8 + q;
                af[mi][0] = tf32u(ap[0]);
                af[mi][1] = tf32u(ap[8 * GPAD]);
                af[mi][2] = tf32u(ap[4]);
                af[mi][3] = tf32u(ap[8 * GPAD + 4]);
            }
            #pragma unroll
            for (int ni = 0; ni < 8; ni++) {
                const float* wp = Ws + (n0 + ni * 8 + g) * GPAD + kc * 8 + q;
                uint32_t b0 = tf32u(wp[0]);
                uint32_t b1 = tf32u(wp[4]);
                mma8(acc[0][ni], af[0], b0, b1);
                mma8(acc[1][ni], af[1], b0, b1);
            }
        }
    }

    #pragma unroll
    for (int mi = 0; mi < 2; mi++) {
        const int r0 = bm + wr * 32 + mi * 16 + g;
        #pragma unroll
        for (int ni = 0; ni < 8; ni++) {
            const int col = bn + wc * 64 + ni * 8 + 2 * q;
            *(float2*)(C + (size_t)r0 * E + col) =
                make_float2(acc[mi][ni][0], acc[mi][ni][1]);
            *(float2*)(C + (size_t)(r0 + 8) * E + col) =
                make_float2(acc[mi][ni][2], acc[mi][ni][3]);
        }
    }
}

// ===========================================================================
// Register-resident causal flash attention (mma.m16n8k8 tf32).
// Longest-first CTA ordering.
// ===========================================================================
__global__ __launch_bounds__(128) void attn_tc() {
    __shared__ float sm[8192];

    const int tid = threadIdx.x;
    const int w = tid >> 5, lane = tid & 31;
    const int g = lane >> 2, q = lane & 3;
    const int b = blockIdx.y / H, h = blockIdx.y % H;
    const int qt = gridDim.x - 1 - blockIdx.x;   // longest CTAs first
    const int qbase = qt * 64;

    const float* Qg = g_q + ((size_t)(b * T + qbase)) * E + h * D;
    const float* Kg = g_k + (size_t)b * T * E + h * D;
    const float* Vg = g_v + (size_t)b * T * E + h * D;

    #pragma unroll
    for (int t = 0; t < 8; t++) {
        int slot = tid + t * 128;
        int row = slot >> 4, c4 = slot & 15;
        float4 v = *(const float4*)(Qg + (size_t)row * E + c4 * 4);
        float* dst = &sm[row * 65 + c4 * 4];
        dst[0] = tf32f(v.x * 0.125f); dst[1] = tf32f(v.y * 0.125f);
        dst[2] = tf32f(v.z * 0.125f); dst[3] = tf32f(v.w * 0.125f);
    }
    __syncthreads();

    const int r0 = w * 16 + g;
    uint32_t qa[8][4];
    #pragma unroll
    for (int kc = 0; kc < 8; kc++) {
        qa[kc][0] = __float_as_uint(sm[r0 * 65 + kc * 8 + q]);
        qa[kc][1] = __float_as_uint(sm[(r0 + 8) * 65 + kc * 8 + q]);
        qa[kc][2] = __float_as_uint(sm[r0 * 65 + kc * 8 + q + 4]);
        qa[kc][3] = __float_as_uint(sm[(r0 + 8) * 65 + kc * 8 + q + 4]);
    }

    float oacc[8][4];
    #pragma unroll
    for (int nt = 0; nt < 8; nt++)
        #pragma unroll
        for (int e = 0; e < 4; e++) oacc[nt][e] = 0.f;

    float m0 = -INFINITY, m1 = -INFINITY, l0 = 0.f, l1 = 0.f;
    const int r0g = qbase + r0, r1g = r0g + 8;
    const int s0l = (lane & ~3) | (q >> 1);
    const int s1l = s0l + 2;

    for (int j = 0; j <= qt; j++) {
        __syncthreads();
        const int kbase = j * 64;
        #pragma unroll
        for (int t = 0; t < 8; t++) {
            int slot = tid + t * 128;
            int row = slot >> 4, c4 = slot & 15;
            float4 kv = *(const float4*)(Kg + (size_t)(kbase + row) * E + c4 * 4);
            float4 vv = *(const float4*)(Vg + (size_t)(kbase + row) * E + c4 * 4);
            float ke[4] = {kv.x, kv.y, kv.z, kv.w};
            float ve[4] = {vv.x, vv.y, vv.z, vv.w};
            #pragma unroll
            for (int ee = 0; ee < 4; ee++) {
                int col = c4 * 4 + ee;
                int nt = row >> 3, kc = col >> 3;
                int ln = ((row & 7) << 2) | (col & 3);
                int e  = (col >> 2) & 1;
                sm[((nt * 8 + kc) * 32 + ln) * 2 + e] = tf32f(ke[ee]);
                int kc2 = row >> 3, e2 = (row >> 2) & 1;
                int nt2 = col >> 3;
                int ln2 = ((col & 7) << 2) | (row & 3);
                sm[4096 + ((nt2 * 8 + kc2) * 32 + ln2) * 2 + e2] = tf32f(ve[ee]);
            }
        }
        __syncthreads();

        float sacc[8][4];
        #pragma unroll
        for (int nt = 0; nt < 8; nt++) {
            #pragma unroll
            for (int e = 0; e < 4; e++) sacc[nt][e] = 0.f;
            #pragma unroll
            for (int kc = 0; kc < 8; kc++) {
                float2 bb = *(const float2*)&sm[((nt * 8 + kc) * 32 + lane) * 2];
                mma8(sacc[nt], qa[kc], __float_as_uint(bb.x), __float_as_uint(bb.y));
            }
        }

        if (j == qt) {
            #pragma unroll
            for (int nt = 0; nt < 8; nt++) {
                #pragma unroll
                for (int e = 0; e < 2; e++) {
                    int colg = kbase + nt * 8 + 2 * q + e;
                    if (colg > r0g) sacc[nt][e]     = -INFINITY;
                    if (colg > r1g) sacc[nt][2 + e] = -INFINITY;
                }
            }
        }

        float mx0 = -INFINITY, mx1 = -INFINITY;
        #pragma unroll
        for (int nt = 0; nt < 8; nt++) {
            mx0 = fmaxf(mx0, fmaxf(sacc[nt][0], sacc[nt][1]));
            mx1 = fmaxf(mx1, fmaxf(sacc[nt][2], sacc[nt][3]));
        }
        mx0 = fmaxf(mx0, __shfl_xor_sync(0xffffffffu, mx0, 1));
        mx0 = fmaxf(mx0, __shfl_xor_sync(0xffffffffu, mx0, 2));
        mx1 = fmaxf(mx1, __shfl_xor_sync(0xffffffffu, mx1, 1));
        mx1 = fmaxf(mx1, __shfl_xor_sync(0xffffffffu, mx1, 2));
        float mn0 = fmaxf(m0, mx0), mn1 = fmaxf(m1, mx1);
        float sc0 = __expf(m0 - mn0), sc1 = __expf(m1 - mn1);

        float s0 = 0.f, s1 = 0.f;
        uint32_t pb[8][4];
        #pragma unroll
        for (int nt = 0; nt < 8; nt++) {
            float p0 = __expf(sacc[nt][0] - mn0);
            float p1 = __expf(sacc[nt][1] - mn0);
            float p2 = __expf(sacc[nt][2] - mn1);
            float p3 = __expf(sacc[nt][3] - mn1);
            s0 += p0 + p1; s1 += p2 + p3;
            pb[nt][0] = tf32u(p0); pb[nt][1] = tf32u(p1);
            pb[nt][2] = tf32u(p2); pb[nt][3] = tf32u(p3);
        }
        s0 += __shfl_xor_sync(0xffffffffu, s0, 1);
        s0 += __shfl_xor_sync(0xffffffffu, s0, 2);
        s1 += __shfl_xor_sync(0xffffffffu, s1, 1);
        s1 += __shfl_xor_sync(0xffffffffu, s1, 2);
        l0 = l0 * sc0 + s0; l1 = l1 * sc1 + s1;
        m0 = mn0; m1 = mn1;
        #pragma unroll
        for (int nt = 0; nt < 8; nt++) {
            oacc[nt][0] *= sc0; oacc[nt][1] *= sc0;
            oacc[nt][2] *= sc1; oacc[nt][3] *= sc1;
        }

        #pragma unroll
        for (int kc = 0; kc < 8; kc++) {
            uint32_t v00 = __shfl_sync(0xffffffffu, pb[kc][0], s0l);
            uint32_t v01 = __shfl_sync(0xffffffffu, pb[kc][1], s0l);
            uint32_t v10 = __shfl_sync(0xffffffffu, pb[kc][2], s0l);
            uint32_t v11 = __shfl_sync(0xffffffffu, pb[kc][3], s0l);
            uint32_t v20 = __shfl_sync(0xffffffffu, pb[kc][0], s1l);
            uint32_t v21 = __shfl_sync(0xffffffffu, pb[kc][1], s1l);
            uint32_t v30 = __shfl_sync(0xffffffffu, pb[kc][2], s1l);
            uint32_t v31 = __shfl_sync(0xffffffffu, pb[kc][3], s1l);
            uint32_t pa[4];
            pa[0] = (q & 1) ? v01 : v00;
            pa[1] = (q & 1) ? v11 : v10;
            pa[2] = (q & 1) ? v21 : v20;
            pa[3] = (q & 1) ? v31 : v30;
            #pragma unroll
            for (int nt = 0; nt < 8; nt++) {
                float2 bb = *(const float2*)&sm[4096 + ((nt * 8 + kc) * 32 + lane) * 2];
                mma8(oacc[nt], pa, __float_as_uint(bb.x), __float_as_uint(bb.y));
            }
        }
    }

    const float inv0 = 1.f / l0, inv1 = 1.f / l1;
    float* O0 = g_attn + ((size_t)(b * T + r0g)) * E + h * D;
    float* O1 = g_attn + ((size_t)(b * T + r1g)) * E + h * D;
    #pragma unroll
    for (int nt = 0; nt < 8; nt++) {
        O0[nt * 8 + 2 * q]     = oacc[nt][0] * inv0;
        O0[nt * 8 + 2 * q + 1] = oacc[nt][1] * inv0;
        O1[nt * 8 + 2 * q]     = oacc[nt][2] * inv1;
        O1[nt * 8 + 2 * q + 1] = oacc[nt][3] * inv1;
    }
}

// ===========================================================================
// Inputs: queries, keys, values, mask(unused), Wq, Wk, Wv, Wo
// ===========================================================================
extern "C" void kernel_launch(void* const* d_in, const int* in_sizes, int n_in,
                              void* d_out, int out_size) {
    const float* queries = (const float*)d_in[0];
    const float* keys    = (const float*)d_in[1];
    const float* values  = (const float*)d_in[2];
    const float* Wq      = (const float*)d_in[4];
    const float* Wk      = (const float*)d_in[5];
    const float* Wv      = (const float*)d_in[6];
    const float* Wo      = (const float*)d_in[7];

    float *qp, *kp, *vp, *ap;
    cudaGetSymbolAddress((void**)&qp, g_q);
    cudaGetSymbolAddress((void**)&kp, g_k);
    cudaGetSymbolAddress((void**)&vp, g_v);
    cudaGetSymbolAddress((void**)&ap, g_attn);

    static bool attr_set = false;
    if (!attr_set) {
        cudaFuncSetAttribute(gemm_mma, cudaFuncAttributeMaxDynamicSharedMemorySize,
                             (int)G_SMEM);
        attr_set = true;
    }

    dim3 gg(E / NT, (BSZ * T) / MT);   // (4, 32) = 128 CTAs, one wave
    gemm_mma<<<gg, 512, G_SMEM>>>(queries, Wq, qp);
    gemm_mma<<<gg, 512, G_SMEM>>>(keys,    Wk, kp);
    gemm_mma<<<gg, 512, G_SMEM>>>(values,  Wv, vp);

    attn_tc<<<dim3(T / 64, BSZ * H), 128>>>();

    gemm_mma<<<gg, 512, G_SMEM>>>(ap, Wo, (float*)d_out);
}

// round 8
// speedup vs baseline: 6.8582x; 1.4151x over previous
#include <cuda_runtime.h>
#include <math.h>
#include <stdint.h>

#define BSZ 2
#define T   2048
#define E   1024
#define H   16
#define D   64

__device__ float g_q[BSZ*T*E];
__device__ float g_k[BSZ*T*E];
__device__ float g_v[BSZ*T*E];
__device__ float g_attn[BSZ*T*E];

// ===========================================================================
// Helpers
// ===========================================================================
__device__ __forceinline__ uint32_t su32(const void* p) {
    return (uint32_t)__cvta_generic_to_shared(p);
}
__device__ __forceinline__ float tf32f(float x) {
    uint32_t u; asm("cvt.rna.tf32.f32 %0, %1;" : "=r"(u) : "f"(x));
    return __uint_as_float(u);
}
__device__ __forceinline__ uint32_t tf32u(float x) {
    uint32_t u; asm("cvt.rna.tf32.f32 %0, %1;" : "=r"(u) : "f"(x));
    return u;
}
__device__ __forceinline__ void mma8(float c[4], const uint32_t a[4],
                                     uint32_t b0, uint32_t b1) {
    asm("mma.sync.aligned.m16n8k8.row.col.f32.tf32.tf32.f32 "
        "{%0,%1,%2,%3},{%4,%5,%6,%7},{%8,%9},{%0,%1,%2,%3};"
        : "+f"(c[0]), "+f"(c[1]), "+f"(c[2]), "+f"(c[3])
        : "r"(a[0]), "r"(a[1]), "r"(a[2]), "r"(a[3]), "r"(b0), "r"(b1));
}
__device__ __forceinline__ void cp16(uint32_t dst, const void* src) {
    asm volatile("cp.async.cg.shared.global [%0], [%1], 16;"
                 :: "r"(dst), "l"(src) : "memory");
}
__device__ __forceinline__ void cp_commit() {
    asm volatile("cp.async.commit_group;" ::: "memory");
}
template <int N>
__device__ __forceinline__ void cp_wait() {
    asm volatile("cp.async.wait_group %0;" :: "n"(N) : "memory");
}

// ===========================================================================
// tf32 mma.sync GEMM core: C[M,N] = A[M,K] @ W[N,K]^T
// CTA 128x256, 512 threads (16 warps, warp 32x64), BK=32, 4-stage cp.async.
// cvt=1: round outputs to tf32 (rna) in the epilogue — lets downstream
// attention consume q/k/v without any per-fragment cvt (identical numerics).
// ===========================================================================
#define KDIM 1024
#define MT   128
#define NT   256
#define BKF  32
#define GPAD 36
#define G_AOFF 0
#define G_WOFF (MT*GPAD*4)
#define G_STAGE ((MT+NT)*GPAD*4)             // 55296 B
#define G_SMEM (4*G_STAGE)                   // 221184 B

__device__ __forceinline__ void gemm_core(const float* __restrict__ A,
                                          const float* __restrict__ W,
                                          float* __restrict__ C,
                                          int cvt, float* sg) {
    const uint32_t sbase = su32(sg);
    const int tid  = threadIdx.x;
    const int wid  = tid >> 5, lane = tid & 31;
    const int g    = lane >> 2, q = lane & 3;
    const int wr   = wid & 3;
    const int wc   = wid >> 2;
    const int bm   = blockIdx.y * MT;
    const int bn   = blockIdx.x * NT;

    const float* gA = A + (size_t)bm * KDIM;
    const float* gW = W + (size_t)bn * KDIM;

    auto cp_stage = [&](int s, int kt) {
        const uint32_t base = sbase + s * G_STAGE;
        const int k0 = kt * BKF;
        #pragma unroll
        for (int i = 0; i < 6; i++) {
            int c = tid + i * 512;
            if (c < 1024) {
                int row = c >> 3, ch = c & 7;
                cp16(base + G_AOFF + (row * GPAD + ch * 4) * 4,
                     gA + (size_t)row * KDIM + k0 + ch * 4);
            } else {
                int cc = c - 1024;
                int row = cc >> 3, ch = cc & 7;
                cp16(base + G_WOFF + (row * GPAD + ch * 4) * 4,
                     gW + (size_t)row * KDIM + k0 + ch * 4);
            }
        }
        cp_commit();
    };

    float acc[2][8][4];
    #pragma unroll
    for (int mi = 0; mi < 2; mi++)
        #pragma unroll
        for (int ni = 0; ni < 8; ni++)
            #pragma unroll
            for (int e = 0; e < 4; e++) acc[mi][ni][e] = 0.f;

    cp_stage(0, 0); cp_stage(1, 1); cp_stage(2, 2);

    const int NKT = KDIM / BKF;
    for (int kt = 0; kt < NKT; kt++) {
        cp_wait<2>();
        __syncthreads();
        if (kt + 3 < NKT) cp_stage((kt + 3) & 3, kt + 3);
        else              cp_commit();

        const float* As = sg + ((kt & 3) * G_STAGE) / 4;
        const float* Ws = As + MT * GPAD;
        const int m0 = wr * 32, n0 = wc * 64;

        #pragma unroll
        for (int kc = 0; kc < 4; kc++) {
            uint32_t af[2][4];
            #pragma unroll
            for (int mi = 0; mi < 2; mi++) {
                const float* ap = As + (m0 + mi * 16 + g) * GPAD + kc * 8 + q;
                af[mi][0] = tf32u(ap[0]);
                af[mi][1] = tf32u(ap[8 * GPAD]);
                af[mi][2] = tf32u(ap[4]);
                af[mi][3] = tf32u(ap[8 * GPAD + 4]);
            }
            #pragma unroll
            for (int ni = 0; ni < 8; ni++) {
                const float* wp = Ws + (n0 + ni * 8 + g) * GPAD + kc * 8 + q;
                uint32_t b0 = tf32u(wp[0]);
                uint32_t b1 = tf32u(wp[4]);
                mma8(acc[0][ni], af[0], b0, b1);
                mma8(acc[1][ni], af[1], b0, b1);
            }
        }
    }

    #pragma unroll
    for (int mi = 0; mi < 2; mi++) {
        const int r0 = bm + wr * 32 + mi * 16 + g;
        #pragma unroll
        for (int ni = 0; ni < 8; ni++) {
            const int col = bn + wc * 64 + ni * 8 + 2 * q;
            float o00 = acc[mi][ni][0], o01 = acc[mi][ni][1];
            float o10 = acc[mi][ni][2], o11 = acc[mi][ni][3];
            if (cvt) { o00 = tf32f(o00); o01 = tf32f(o01);
                       o10 = tf32f(o10); o11 = tf32f(o11); }
            *(float2*)(C + (size_t)r0 * E + col)       = make_float2(o00, o01);
            *(float2*)(C + (size_t)(r0 + 8) * E + col) = make_float2(o10, o11);
        }
    }
}

__global__ __launch_bounds__(512, 1) void gemm_qkv(
        const float* __restrict__ Aq, const float* __restrict__ Ak,
        const float* __restrict__ Av, const float* __restrict__ Wq,
        const float* __restrict__ Wk, const float* __restrict__ Wv,
        float* Cq, float* Ck, float* Cv) {
    extern __shared__ float sg[];
    const float* A; const float* W; float* C;
    if (blockIdx.z == 0)      { A = Aq; W = Wq; C = Cq; }
    else if (blockIdx.z == 1) { A = Ak; W = Wk; C = Ck; }
    else                      { A = Av; W = Wv; C = Cv; }
    gemm_core(A, W, C, 1, sg);
}

__global__ __launch_bounds__(512, 1) void gemm_out(const float* __restrict__ A,
                                                   const float* __restrict__ W,
                                                   float* __restrict__ C) {
    extern __shared__ float sg[];
    gemm_core(A, W, C, 0, sg);
}

// ===========================================================================
// Causal flash attention, mma.m16n8k8 tf32, register-resident S/P/O.
// 256 threads (8 warps), 128 query rows/CTA (16 per warp), 64-key tiles.
// K/V staged ROW-MAJOR via cp.async (double-buffered); B-fragments read with
// two conflict-free scalar LDS each (K stride 68: bank=4n+k; V stride 72:
// bank=8k+n). q/k/v are tf32-rounded by the projection epilogue -> no cvt
// anywhere in the hot loop. Per-warp skip of fully-masked tiles.
// ===========================================================================
#define APK 68
#define APV 72
#define AKBUF (64*APK)                        // 4352 floats
#define AVBUF (64*APV)                        // 4608 floats
#define A_SMEM ((2*AKBUF + 2*AVBUF)*4)        // 71680 B

__global__ __launch_bounds__(256, 2) void attn_tc() {
    extern __shared__ float sm[];
    const uint32_t sbase = su32(sm);

    const int tid = threadIdx.x;
    const int w = tid >> 5, lane = tid & 31;
    const int g = lane >> 2, q = lane & 3;
    const int b = blockIdx.y / H, h = blockIdx.y % H;
    const int qt = gridDim.x - 1 - blockIdx.x;   // longest CTAs first
    const int qbase = qt * 128;
    const int jmax = 2 * qt + 1;

    const float* Kg = g_k + (size_t)b * T * E + h * D;
    const float* Vg = g_v + (size_t)b * T * E + h * D;

    // Q A-fragments straight from gmem (already tf32; 0.125 scale is exact)
    const float* Q0 = g_q + (size_t)(b * T + qbase + w * 16 + g) * E + h * D;
    uint32_t qa[8][4];
    #pragma unroll
    for (int kc = 0; kc < 8; kc++) {
        qa[kc][0] = __float_as_uint(Q0[kc * 8 + q] * 0.125f);
        qa[kc][1] = __float_as_uint(Q0[(size_t)8 * E + kc * 8 + q] * 0.125f);
        qa[kc][2] = __float_as_uint(Q0[kc * 8 + q + 4] * 0.125f);
        qa[kc][3] = __float_as_uint(Q0[(size_t)8 * E + kc * 8 + q + 4] * 0.125f);
    }

    auto stage = [&](int j) {
        const int buf = j & 1;
        const float* Kt = Kg + (size_t)(j * 64) * E;
        const float* Vt = Vg + (size_t)(j * 64) * E;
        const uint32_t kdst = sbase + buf * (AKBUF * 4);
        const uint32_t vdst = sbase + (2 * AKBUF + buf * AVBUF) * 4;
        #pragma unroll
        for (int t = 0; t < 4; t++) {
            int c = tid + t * 256;               // 0..1023
            int row = c >> 4, ch = c & 15;
            cp16(kdst + (row * APK + ch * 4) * 4, Kt + (size_t)row * E + ch * 4);
            cp16(vdst + (row * APV + ch * 4) * 4, Vt + (size_t)row * E + ch * 4);
        }
        cp_commit();
    };

    float oacc[8][4];
    #pragma unroll
    for (int nt = 0; nt < 8; nt++)
        #pragma unroll
        for (int e = 0; e < 4; e++) oacc[nt][e] = 0.f;

    float m0 = -INFINITY, m1 = -INFINITY, l0 = 0.f, l1 = 0.f;
    const int r0g = qbase + w * 16 + g, r1g = r0g + 8;
    const int wmaxrow = qbase + w * 16 + 15;     // last row this warp owns
    const int s0l = (lane & ~3) | (q >> 1);
    const int s1l = s0l + 2;
    const int kboff = g * APK + q;               // K b-frag base (n=g, k=q)
    const int vboff = q * APV + g;               // V b-frag base (k=q, n=g)

    stage(0);

    for (int j = 0; j <= jmax; j++) {
        __syncthreads();                         // prev compute done everywhere
        if (j < jmax) stage(j + 1);
        else          cp_commit();               // keep wait-group math valid
        cp_wait<1>();                            // this thread's tile-j chunks done
        __syncthreads();                         // all threads' chunks done

        const int kbase = j * 64;
        if (kbase > wmaxrow) continue;           // tile fully masked for warp

        const float* Ks = sm + (j & 1) * AKBUF;
        const float* Vs = sm + 2 * AKBUF + (j & 1) * AVBUF;

        // S = Q @ K^T
        float sacc[8][4];
        #pragma unroll
        for (int nt = 0; nt < 8; nt++) {
            #pragma unroll
            for (int e = 0; e < 4; e++) sacc[nt][e] = 0.f;
            const float* kp = Ks + nt * 8 * APK + kboff;
            #pragma unroll
            for (int kc = 0; kc < 8; kc++) {
                mma8(sacc[nt], qa[kc],
                     __float_as_uint(kp[kc * 8]),
                     __float_as_uint(kp[kc * 8 + 4]));
            }
        }

        // Causal mask (only tiles overlapping the diagonal)
        if (kbase + 63 > r0g) {
            #pragma unroll
            for (int nt = 0; nt < 8; nt++) {
                #pragma unroll
                for (int e = 0; e < 2; e++) {
                    int colg = kbase + nt * 8 + 2 * q + e;
                    if (colg > r0g) sacc[nt][e]     = -INFINITY;
                    if (colg > r1g) sacc[nt][2 + e] = -INFINITY;
                }
            }
        }

        // Online softmax (registers + quad shuffles)
        float mx0 = -INFINITY, mx1 = -INFINITY;
        #pragma unroll
        for (int nt = 0; nt < 8; nt++) {
            mx0 = fmaxf(mx0, fmaxf(sacc[nt][0], sacc[nt][1]));
            mx1 = fmaxf(mx1, fmaxf(sacc[nt][2], sacc[nt][3]));
        }
        mx0 = fmaxf(mx0, __shfl_xor_sync(0xffffffffu, mx0, 1));
        mx0 = fmaxf(mx0, __shfl_xor_sync(0xffffffffu, mx0, 2));
        mx1 = fmaxf(mx1, __shfl_xor_sync(0xffffffffu, mx1, 1));
        mx1 = fmaxf(mx1, __shfl_xor_sync(0xffffffffu, mx1, 2));
        float mn0 = fmaxf(m0, mx0), mn1 = fmaxf(m1, mx1);
        float sc0 = __expf(m0 - mn0), sc1 = __expf(m1 - mn1);

        float s0 = 0.f, s1 = 0.f;
        #pragma unroll
        for (int nt = 0; nt < 8; nt++) {
            float p0 = __expf(sacc[nt][0] - mn0);
            float p1 = __expf(sacc[nt][1] - mn0);
            float p2 = __expf(sacc[nt][2] - mn1);
            float p3 = __expf(sacc[nt][3] - mn1);
            s0 += p0 + p1; s1 += p2 + p3;
            sacc[nt][0] = __uint_as_float(tf32u(p0));
            sacc[nt][1] = __uint_as_float(tf32u(p1));
            sacc[nt][2] = __uint_as_float(tf32u(p2));
            sacc[nt][3] = __uint_as_float(tf32u(p3));
        }
        s0 += __shfl_xor_sync(0xffffffffu, s0, 1);
        s0 += __shfl_xor_sync(0xffffffffu, s0, 2);
        s1 += __shfl_xor_sync(0xffffffffu, s1, 1);
        s1 += __shfl_xor_sync(0xffffffffu, s1, 2);
        l0 = l0 * sc0 + s0; l1 = l1 * sc1 + s1;
        m0 = mn0; m1 = mn1;
        #pragma unroll
        for (int nt = 0; nt < 8; nt++) {
            oacc[nt][0] *= sc0; oacc[nt][1] *= sc0;
            oacc[nt][2] *= sc1; oacc[nt][3] *= sc1;
        }

        // O += P @ V : transpose P acc-layout -> A-layout via quad shuffles
        #pragma unroll
        for (int kc = 0; kc < 8; kc++) {
            uint32_t p0 = __float_as_uint(sacc[kc][0]);
            uint32_t p1 = __float_as_uint(sacc[kc][1]);
            uint32_t p2 = __float_as_uint(sacc[kc][2]);
            uint32_t p3 = __float_as_uint(sacc[kc][3]);
            uint32_t v00 = __shfl_sync(0xffffffffu, p0, s0l);
            uint32_t v01 = __shfl_sync(0xffffffffu, p1, s0l);
            uint32_t v10 = __shfl_sync(0xffffffffu, p2, s0l);
            uint32_t v11 = __shfl_sync(0xffffffffu, p3, s0l);
            uint32_t v20 = __shfl_sync(0xffffffffu, p0, s1l);
            uint32_t v21 = __shfl_sync(0xffffffffu, p1, s1l);
            uint32_t v30 = __shfl_sync(0xffffffffu, p2, s1l);
            uint32_t v31 = __shfl_sync(0xffffffffu, p3, s1l);
            uint32_t pa[4];
            pa[0] = (q & 1) ? v01 : v00;
            pa[1] = (q & 1) ? v11 : v10;
            pa[2] = (q & 1) ? v21 : v20;
            pa[3] = (q & 1) ? v31 : v30;
            const float* vp = Vs + kc * 8 * APV + vboff;
            #pragma unroll
            for (int nt = 0; nt < 8; nt++) {
                mma8(oacc[nt], pa,
                     __float_as_uint(vp[nt * 8]),
                     __float_as_uint(vp[nt * 8 + 4 * APV]));
            }
        }
    }

    const float inv0 = 1.f / l0, inv1 = 1.f / l1;
    float* O0 = g_attn + ((size_t)(b * T + r0g)) * E + h * D;
    float* O1 = g_attn + ((size_t)(b * T + r1g)) * E + h * D;
    #pragma unroll
    for (int nt = 0; nt < 8; nt++) {
        O0[nt * 8 + 2 * q]     = oacc[nt][0] * inv0;
        O0[nt * 8 + 2 * q + 1] = oacc[nt][1] * inv0;
        O1[nt * 8 + 2 * q]     = oacc[nt][2] * inv1;
        O1[nt * 8 + 2 * q + 1] = oacc[nt][3] * inv1;
    }
}

// ===========================================================================
// Inputs: queries, keys, values, mask(unused), Wq, Wk, Wv, Wo
// ===========================================================================
extern "C" void kernel_launch(void* const* d_in, const int* in_sizes, int n_in,
                              void* d_out, int out_size) {
    const float* queries = (const float*)d_in[0];
    const float* keys    = (const float*)d_in[1];
    const float* values  = (const float*)d_in[2];
    const float* Wq      = (const float*)d_in[4];
    const float* Wk      = (const float*)d_in[5];
    const float* Wv      = (const float*)d_in[6];
    const float* Wo      = (const float*)d_in[7];

    float *qp, *kp, *vp, *ap;
    cudaGetSymbolAddress((void**)&qp, g_q);
    cudaGetSymbolAddress((void**)&kp, g_k);
    cudaGetSymbolAddress((void**)&vp, g_v);
    cudaGetSymbolAddress((void**)&ap, g_attn);

    static bool attr_set = false;
    if (!attr_set) {
        cudaFuncSetAttribute(gemm_qkv, cudaFuncAttributeMaxDynamicSharedMemorySize, (int)G_SMEM);
        cudaFuncSetAttribute(gemm_out, cudaFuncAttributeMaxDynamicSharedMemorySize, (int)G_SMEM);
        cudaFuncSetAttribute(attn_tc,  cudaFuncAttributeMaxDynamicSharedMemorySize, (int)A_SMEM);
        attr_set = true;
    }

    dim3 gq(E / NT, (BSZ * T) / MT, 3);     // fused Q/K/V projections
    gemm_qkv<<<gq, 512, G_SMEM>>>(queries, keys, values, Wq, Wk, Wv, qp, kp, vp);

    attn_tc<<<dim3(T / 128, BSZ * H), 256, A_SMEM>>>();

    dim3 gg(E / NT, (BSZ * T) / MT);
    gemm_out<<<gg, 512, G_SMEM>>>(ap, Wo, (float*)d_out);
}